// round 4
// baseline (speedup 1.0000x reference)
#include <cuda_runtime.h>
#include <cuda_bf16.h>

#define EPS 1e-16f
#define W 1024
#define H 1024
#define ROWS 2          // output rows per thread/block
#define TPB 256         // 256 threads * 4 px = 1024 = full row width

__global__ __launch_bounds__(TPB, 8)
void curvature_kernel(const float* __restrict__ u, float* __restrict__ out) {
    // block handles ROWS rows x full width of one batch image
    const int tile = blockIdx.x;            // b * (H/ROWS) + row-tile
    const int b    = tile >> 9;             // H/ROWS = 512 tiles per image
    const int x0   = (tile & 511) * ROWS;   // first output row
    const int y    = threadIdx.x * 4;       // first output col (float4 granule)
    const int lane = threadIdx.x & 31;

    const float* ub = u   + (size_t)b * (H * W);
    float*       ob = out + (size_t)b * (H * W);

    // ---- 4 row-vectors (rows x0-1 .. x0+2) at col y, reflect-clamped in x ----
    float rows[ROWS + 2][4];
    #pragma unroll
    for (int i = 0; i < ROWS + 2; ++i) {
        int r = x0 - 1 + i;
        r = (r < 0) ? 1 : ((r >= H) ? (H - 2) : r);
        float4 v = *reinterpret_cast<const float4*>(ub + (size_t)r * W + y);
        rows[i][0] = v.x; rows[i][1] = v.y; rows[i][2] = v.z; rows[i][3] = v.w;
    }

    // ---- side columns via warp shuffle (warp covers 128 contiguous cols) ----
    // lftv[k] = u[reflect(x0+k),   y-1]  == lane-1's rows[k+1][3]
    // rgtv[k] = u[reflect(x0-1+k), y+4]  == lane+1's rows[k][0]
    float lftv[ROWS + 1], rgtv[ROWS + 1];
    #pragma unroll
    for (int k = 0; k <= ROWS; ++k) {
        lftv[k] = __shfl_up_sync(0xffffffffu, rows[k + 1][3], 1);
        rgtv[k] = __shfl_down_sync(0xffffffffu, rows[k][0], 1);
    }
    // warp-seam / image-edge fixups (2 active lanes per warp)
    if (lane == 0) {
        #pragma unroll
        for (int k = 0; k <= ROWS; ++k) {
            int r = x0 + k;                    // never < 0
            r = (r >= H) ? (H - 2) : r;
            lftv[k] = (y == 0) ? rows[k + 1][1]                 // reflect: col -1 -> 1
                               : __ldg(ub + (size_t)r * W + (y - 1));
        }
    }
    if (lane == 31) {
        #pragma unroll
        for (int k = 0; k <= ROWS; ++k) {
            int r = x0 - 1 + k;                // never >= H
            r = (r < 0) ? 1 : r;
            rgtv[k] = (y + 4 == W) ? rows[k][2]                 // reflect: col W -> W-2
                                   : __ldg(ub + (size_t)r * W + (y + 4));
        }
    }

    // ---- compute ROWS x 4 outputs ----
    #pragma unroll
    for (int i = 0; i < ROWS; ++i) {
        float res[4];
        #pragma unroll
        for (int j = 0; j < 4; ++j) {
            const float c    = rows[i + 1][j];                        // u[x, y+j]
            const float up   = rows[i][j];                            // u[x-1, y+j]
            const float dn   = rows[i + 2][j];                        // u[x+1, y+j]
            const float rgt  = (j < 3) ? rows[i + 1][j + 1] : rgtv[i + 1]; // u[x, y+j+1]
            const float lft  = (j > 0) ? rows[i + 1][j - 1] : lftv[i];     // u[x, y+j-1]
            const float up_r = (j < 3) ? rows[i][j + 1]     : rgtv[i];     // u[x-1, y+j+1]
            const float dn_l = (j > 0) ? rows[i + 2][j - 1] : lftv[i + 1]; // u[x+1, y+j-1]

            const float dxf  = dn   - c;
            const float dxb  = c    - up;
            const float dyf  = rgt  - c;
            const float dyb  = c    - lft;
            const float dsbf = up_r - up;    // u[x-1,y+1] - u[x-1,y]
            const float dslf = dn_l - lft;   // u[x+1,y-1] - u[x,  y-1]

            const float invF = rsqrtf(fmaf(dxf, dxf, fmaf(dyf, dyf, EPS)));
            const float invG = rsqrtf(fmaf(dxb, dxb, fmaf(dsbf, dsbf, EPS)));
            const float invH = rsqrtf(fmaf(dslf, dslf, fmaf(dyb, dyb, EPS)));

            res[j] = (dxf + dyf) * invF - dxb * invG - dyb * invH;
        }
        float4 o;
        o.x = res[0]; o.y = res[1]; o.z = res[2]; o.w = res[3];
        *reinterpret_cast<float4*>(ob + (size_t)(x0 + i) * W + y) = o;
    }
}

extern "C" void kernel_launch(void* const* d_in, const int* in_sizes, int n_in,
                              void* d_out, int out_size) {
    const float* u = (const float*)d_in[0];
    float* out = (float*)d_out;
    const int batch = in_sizes[0] / (H * W);   // 16
    const int blocks = batch * (H / ROWS);     // 8192
    curvature_kernel<<<blocks, TPB>>>(u, out);
}